// round 1
// baseline (speedup 1.0000x reference)
#include <cuda_runtime.h>
#include <math.h>

// Problem constants
// B=4096, N=50, M=64, D=64, K_flat=3200, hidden 512/256/128
#define BATCH 4096

// Scratch (no allocations allowed -> device globals)
__device__ float g_feats[4096 * 3200];   // 52.4 MB
__device__ float g_s[4096 * 64];
__device__ float g_x[4096 * 192];        // concat(l_z, l_p_in, l_p_out)
__device__ float g_h0[4096 * 512];
__device__ float g_h1[4096 * 256];
__device__ float g_h2[4096 * 128];

// ---------------------------------------------------------------------------
// Kernel 1: gather feats, write g_feats / g_s, fuse l_p_in into g_x[:,64:128]
// grid 4096, block 256
// ---------------------------------------------------------------------------
__global__ void gather_kernel(const float* __restrict__ fv,
                              const int* __restrict__ idx,
                              const float* __restrict__ emb,
                              const float* __restrict__ theta)
{
    const int b = blockIdx.x;
    const int t = threadIdx.x;
    __shared__ float feats[50 * 65];   // padded rows (stride 65) for bank-free col access
    __shared__ float sq[50];
    __shared__ int   sidx[50];
    __shared__ float sfv[50];

    if (t < 50) { sidx[t] = idx[b * 50 + t]; sfv[t] = fv[b * 50 + t]; }
    __syncthreads();

    for (int j = t; j < 3200; j += 256) {
        int n = j >> 6, m = j & 63;
        feats[n * 65 + m] = emb[sidx[n] * 64 + m] * sfv[n];
    }
    __syncthreads();

    if (t < 64) {  // s[b,m] = sum_n feats
        float acc = 0.f;
        #pragma unroll
        for (int n = 0; n < 50; n++) acc += feats[n * 65 + t];
        g_s[b * 64 + t] = acc;
    }
    if (t >= 64 && t < 114) {  // sq[n] = sum_m feats^2
        int n = t - 64;
        float acc = 0.f;
        #pragma unroll
        for (int m = 0; m < 64; m++) { float v = feats[n * 65 + m]; acc += v * v; }
        sq[n] = acc;
    }
    __syncthreads();

    // spill feats to global (flat k = n*64+m, coalesced)
    for (int j = t; j < 3200; j += 256)
        g_feats[b * 3200 + j] = feats[(j >> 6) * 65 + (j & 63)];

    // l_p_in[b,d] = sum_n theta[d,n]^2 * sq[n]
    if (t < 64) {
        float acc = 0.f;
        #pragma unroll
        for (int n = 0; n < 50; n++) { float th = theta[t * 50 + n]; acc += th * th * sq[n]; }
        g_x[b * 192 + 64 + t] = acc;
    }
}

// ---------------------------------------------------------------------------
// Kernel 2: l_p_out[b,d] = s[b,:] @ quad_w[d] @ s[b,:]
// 16 batch rows per block, 256 threads (16 threads per row, 4 m' each)
// grid 256
// ---------------------------------------------------------------------------
__global__ void opnn_kernel(const float* __restrict__ quad)
{
    __shared__ float s[16][65];
    __shared__ __align__(16) float Qt[64][68];  // Qt[n][m'] = Q[m'][n]; stride 68 keeps 16B align
    const int tid = threadIdx.x;
    const int b0 = blockIdx.x * 16;

    for (int j = tid; j < 16 * 64; j += 256)
        s[j >> 6][j & 63] = g_s[b0 * 64 + j];
    __syncthreads();

    const int bb = tid >> 4;       // 0..15 local batch
    const int sub = tid & 15;      // m' quarter group
    float smp[4];
    #pragma unroll
    for (int i = 0; i < 4; i++) smp[i] = s[bb][sub * 4 + i];

    for (int d = 0; d < 64; d++) {
        // load Q[d] transposed
        for (int j = tid; j < 4096; j += 256) {
            int mp = j >> 6, n = j & 63;
            Qt[n][mp] = quad[d * 4096 + j];
        }
        __syncthreads();

        float inner[4] = {0.f, 0.f, 0.f, 0.f};
        #pragma unroll 8
        for (int n = 0; n < 64; n++) {
            float sn = s[bb][n];
            float4 q = *reinterpret_cast<const float4*>(&Qt[n][sub * 4]);
            inner[0] += q.x * sn;
            inner[1] += q.y * sn;
            inner[2] += q.z * sn;
            inner[3] += q.w * sn;
        }
        float part = smp[0] * inner[0] + smp[1] * inner[1]
                   + smp[2] * inner[2] + smp[3] * inner[3];
        #pragma unroll
        for (int off = 8; off > 0; off >>= 1)
            part += __shfl_down_sync(0xffffffffu, part, off, 16);
        if (sub == 0) g_x[(b0 + bb) * 192 + 128 + d] = part;
        __syncthreads();
    }
}

// ---------------------------------------------------------------------------
// Generic fp32 tiled GEMM: C = A[M,K] @ B (+ optional BN+ReLU epilogue)
// B layout: B_NK ? [N,K] row-major (C = A @ B^T) : [K,N] row-major
// A assumed lda == K. block 256 threads, grid (N/BN, M/BM).
// ---------------------------------------------------------------------------
template<int BM, int BN, int BK, int TM, int TN, bool B_NK, int EPI>
__global__ void gemm_kernel(const float* __restrict__ A, const float* __restrict__ B,
                            float* __restrict__ C, int M, int N, int K,
                            int ldc, int coff,
                            const float* __restrict__ bias, const float* __restrict__ gam,
                            const float* __restrict__ bet, const float* __restrict__ mu,
                            const float* __restrict__ var)
{
    __shared__ float As[BK][BM + 4];
    __shared__ float Bs[BK][BN + 4];
    const int tid = threadIdx.x;
    const int tx = tid % (BN / TN);
    const int ty = tid / (BN / TN);
    const int rowBase = blockIdx.y * BM;
    const int colBase = blockIdx.x * BN;

    float acc[TM][TN];
    #pragma unroll
    for (int i = 0; i < TM; i++)
        #pragma unroll
        for (int j = 0; j < TN; j++) acc[i][j] = 0.f;

    for (int k0 = 0; k0 < K; k0 += BK) {
        #pragma unroll
        for (int j = tid; j < BM * BK; j += 256) {
            int r = j / BK, c = j % BK;
            As[c][r] = A[(rowBase + r) * K + k0 + c];
        }
        if (B_NK) {
            #pragma unroll
            for (int j = tid; j < BN * BK; j += 256) {
                int r = j / BK, c = j % BK;   // r = n local, c = k local
                Bs[c][r] = B[(colBase + r) * K + k0 + c];
            }
        } else {
            #pragma unroll
            for (int j = tid; j < BN * BK; j += 256) {
                int r = j / BN, c = j % BN;   // r = k local, c = n local
                Bs[r][c] = B[(k0 + r) * N + colBase + c];
            }
        }
        __syncthreads();

        #pragma unroll
        for (int kk = 0; kk < BK; kk++) {
            float ra[TM], rb[TN];
            #pragma unroll
            for (int i = 0; i < TM; i++) ra[i] = As[kk][ty * TM + i];
            #pragma unroll
            for (int j = 0; j < TN; j++) rb[j] = Bs[kk][tx * TN + j];
            #pragma unroll
            for (int i = 0; i < TM; i++)
                #pragma unroll
                for (int j = 0; j < TN; j++)
                    acc[i][j] += ra[i] * rb[j];
        }
        __syncthreads();
    }

    #pragma unroll
    for (int j = 0; j < TN; j++) {
        int col = colBase + tx * TN + j;
        float scale = 1.f, shift = 0.f;
        if (EPI == 1) {
            scale = gam[col] * rsqrtf(var[col] + 1e-3f);
            shift = (bias[col] - mu[col]) * scale + bet[col];
        }
        #pragma unroll
        for (int i = 0; i < TM; i++) {
            int row = rowBase + ty * TM + i;
            float v = acc[i][j];
            if (EPI == 1) v = fmaxf(v * scale + shift, 0.f);
            C[row * ldc + coff + col] = v;
        }
    }
}

// ---------------------------------------------------------------------------
// Kernel: final dense [4096,128]@[128,1] + sigmoid; one warp per batch row
// grid 512, block 256
// ---------------------------------------------------------------------------
__global__ void final_kernel(const float* __restrict__ Wout,
                             const float* __restrict__ bout,
                             float* __restrict__ out)
{
    const int warp = (blockIdx.x * blockDim.x + threadIdx.x) >> 5;
    const int lane = threadIdx.x & 31;
    if (warp >= BATCH) return;
    const float* h = &g_h2[warp * 128];
    float acc = h[lane]       * Wout[lane]
              + h[lane + 32]  * Wout[lane + 32]
              + h[lane + 64]  * Wout[lane + 64]
              + h[lane + 96]  * Wout[lane + 96];
    #pragma unroll
    for (int off = 16; off > 0; off >>= 1)
        acc += __shfl_down_sync(0xffffffffu, acc, off);
    if (lane == 0) {
        float z = acc + bout[0];
        out[warp] = 1.f / (1.f + expf(-z));
    }
}

// ---------------------------------------------------------------------------
extern "C" void kernel_launch(void* const* d_in, const int* in_sizes, int n_in,
                              void* d_out, int out_size)
{
    const float* fv    = (const float*)d_in[0];
    const int*   idx   = (const int*)  d_in[1];
    const float* emb   = (const float*)d_in[2];
    const float* LS    = (const float*)d_in[3];   // [64, 3200] (d-major flat)
    const float* theta = (const float*)d_in[4];
    const float* quad  = (const float*)d_in[5];
    const float* W0  = (const float*)d_in[6];
    const float* b0  = (const float*)d_in[7];
    const float* gm0 = (const float*)d_in[8];
    const float* be0 = (const float*)d_in[9];
    const float* m0  = (const float*)d_in[10];
    const float* v0  = (const float*)d_in[11];
    const float* W1  = (const float*)d_in[12];
    const float* b1  = (const float*)d_in[13];
    const float* gm1 = (const float*)d_in[14];
    const float* be1 = (const float*)d_in[15];
    const float* m1  = (const float*)d_in[16];
    const float* v1  = (const float*)d_in[17];
    const float* W2  = (const float*)d_in[18];
    const float* b2  = (const float*)d_in[19];
    const float* gm2 = (const float*)d_in[20];
    const float* be2 = (const float*)d_in[21];
    const float* m2  = (const float*)d_in[22];
    const float* v2  = (const float*)d_in[23];
    const float* Wout = (const float*)d_in[24];
    const float* bout = (const float*)d_in[25];
    float* out = (float*)d_out;

    float *p_feats, *p_x, *p_h0, *p_h1;
    cudaGetSymbolAddress((void**)&p_feats, g_feats);
    cudaGetSymbolAddress((void**)&p_x, g_x);
    cudaGetSymbolAddress((void**)&p_h0, g_h0);
    cudaGetSymbolAddress((void**)&p_h1, g_h1);
    float* p_h2;
    cudaGetSymbolAddress((void**)&p_h2, g_h2);

    // 1) gather + l_p_in
    gather_kernel<<<BATCH, 256>>>(fv, idx, emb, theta);

    // 2) l_z = feats @ LS^T : [4096,3200] x [64,3200]^T -> g_x[:,0:64]
    gemm_kernel<32, 64, 16, 2, 4, true, 0>
        <<<dim3(1, BATCH / 32), 256>>>(p_feats, LS, p_x, BATCH, 64, 3200,
                                       192, 0, nullptr, nullptr, nullptr, nullptr, nullptr);

    // 3) l_p_out -> g_x[:,128:192]
    opnn_kernel<<<BATCH / 16, 256>>>(quad);

    // 4) MLP with fused BN(inference) + ReLU
    gemm_kernel<128, 64, 16, 8, 4, false, 1>
        <<<dim3(512 / 64, BATCH / 128), 256>>>(p_x, W0, p_h0, BATCH, 512, 192,
                                               512, 0, b0, gm0, be0, m0, v0);
    gemm_kernel<128, 64, 16, 8, 4, false, 1>
        <<<dim3(256 / 64, BATCH / 128), 256>>>(p_h0, W1, p_h1, BATCH, 256, 512,
                                               256, 0, b1, gm1, be1, m1, v1);
    gemm_kernel<128, 64, 16, 8, 4, false, 1>
        <<<dim3(128 / 64, BATCH / 128), 256>>>(p_h1, W2, p_h2, BATCH, 128, 256,
                                               128, 0, b2, gm2, be2, m2, v2);

    // 5) output layer + sigmoid
    final_kernel<<<BATCH * 32 / 256, 256>>>(Wout, bout, out);
}

// round 2
// speedup vs baseline: 2.7717x; 2.7717x over previous
#include <cuda_runtime.h>
#include <math.h>

#define BATCH 4096

// Scratch (device globals; no allocations allowed)
__device__ float g_s[4096 * 64];
__device__ float g_x[4096 * 192];        // concat(l_z, l_p_in, l_p_out)
__device__ float g_qr[64 * 4096];        // quad transposed: Qr[m][d*64+n]
__device__ float g_h0[4096 * 512];
__device__ float g_h1[4096 * 256];
__device__ float g_h2[4096 * 128];

// ---------------------------------------------------------------------------
// Prep: Qr[m*4096 + d*64 + n] = quad[d*4096 + m*64 + n]
// ---------------------------------------------------------------------------
__global__ void prep_qr_kernel(const float* __restrict__ quad)
{
    int o = blockIdx.x * 256 + threadIdx.x;      // grid 1024 x 256 = 262144
    int m = o >> 12;
    int rest = o & 4095;                         // d*64 + n
    int d = rest >> 6, n = rest & 63;
    g_qr[o] = quad[d * 4096 + m * 64 + n];
}

// ---------------------------------------------------------------------------
// Gather: per-batch s[m], sq[n] -> l_p_in; zero the l_z slot for atomics.
// grid 4096, block 256
// ---------------------------------------------------------------------------
__global__ void gather_kernel(const float* __restrict__ fv,
                              const int* __restrict__ idx,
                              const float* __restrict__ emb,
                              const float* __restrict__ theta)
{
    const int b = blockIdx.x;
    const int t = threadIdx.x;
    __shared__ float feats[50 * 65];
    __shared__ float sq[50];
    __shared__ int   sidx[50];
    __shared__ float sfv[50];

    if (t < 50) { sidx[t] = idx[b * 50 + t]; sfv[t] = fv[b * 50 + t]; }
    __syncthreads();

    for (int j = t; j < 3200; j += 256) {
        int n = j >> 6, m = j & 63;
        feats[n * 65 + m] = emb[sidx[n] * 64 + m] * sfv[n];
    }
    __syncthreads();

    if (t < 64) {  // s[b,m]
        float acc = 0.f;
        #pragma unroll
        for (int n = 0; n < 50; n++) acc += feats[n * 65 + t];
        g_s[b * 64 + t] = acc;
        g_x[b * 192 + t] = 0.f;   // zero l_z region for atomic accumulation
    }
    if (t >= 64 && t < 114) {  // sq[n]
        int n = t - 64;
        float acc = 0.f;
        #pragma unroll
        for (int m = 0; m < 64; m++) { float v = feats[n * 65 + m]; acc += v * v; }
        sq[n] = acc;
    }
    __syncthreads();

    if (t < 64) {  // l_p_in[b,d]
        float acc = 0.f;
        #pragma unroll
        for (int n = 0; n < 50; n++) { float th = theta[t * 50 + n]; acc += th * th * sq[n]; }
        g_x[b * 192 + 64 + t] = acc;
    }
}

// ---------------------------------------------------------------------------
// l_z fused gather-GEMM: l_z[b,d] += sum_{n in chunk} sum_m feats[b,n,m]*LS[d,n,m]
// BM=64 rows(b), BN=64 cols(d, all), BK=64 (= one field n). grid (64, 5).
// Atomic epilogue into g_x[:, 0:64].
// ---------------------------------------------------------------------------
__global__ void __launch_bounds__(256) lz_kernel(const float* __restrict__ fv,
                                                 const int* __restrict__ idx,
                                                 const float* __restrict__ emb,
                                                 const float* __restrict__ LS)
{
    __shared__ float As[64][68];   // [b][m]
    __shared__ float Bs[64][68];   // [m][d]
    __shared__ int   sidx[64];
    __shared__ float sfv[64];
    const int tid = threadIdx.x;
    const int rowBase = blockIdx.x * 64;
    const int n0 = blockIdx.y * 10;
    const int tx = tid & 15, ty = tid >> 4;

    float acc[4][4];
    #pragma unroll
    for (int i = 0; i < 4; i++)
        #pragma unroll
        for (int j = 0; j < 4; j++) acc[i][j] = 0.f;

    for (int ni = 0; ni < 10; ni++) {
        const int n = n0 + ni;
        if (tid < 64) {
            sidx[tid] = idx[(rowBase + tid) * 50 + n];
            sfv[tid]  = fv[(rowBase + tid) * 50 + n];
        }
        __syncthreads();
        {
            const int m = tid & 63;
            const int r0 = tid >> 6;
            #pragma unroll
            for (int p = 0; p < 16; p++) {          // As[b][m], emb read coalesced in m
                int r = r0 + p * 4;
                As[r][m] = emb[(long)sidx[r] * 64 + m] * sfv[r];
            }
            #pragma unroll
            for (int p = 0; p < 16; p++) {          // Bs[m][d], LS read coalesced in m
                int d = r0 + p * 4;
                Bs[m][d] = LS[d * 3200 + n * 64 + m];
            }
        }
        __syncthreads();
        #pragma unroll 8
        for (int kk = 0; kk < 64; kk++) {
            float ra[4];
            #pragma unroll
            for (int i = 0; i < 4; i++) ra[i] = As[ty * 4 + i][kk];
            float4 b4 = *reinterpret_cast<const float4*>(&Bs[kk][tx * 4]);
            acc[0][0] += ra[0] * b4.x; acc[0][1] += ra[0] * b4.y;
            acc[0][2] += ra[0] * b4.z; acc[0][3] += ra[0] * b4.w;
            acc[1][0] += ra[1] * b4.x; acc[1][1] += ra[1] * b4.y;
            acc[1][2] += ra[1] * b4.z; acc[1][3] += ra[1] * b4.w;
            acc[2][0] += ra[2] * b4.x; acc[2][1] += ra[2] * b4.y;
            acc[2][2] += ra[2] * b4.z; acc[2][3] += ra[2] * b4.w;
            acc[3][0] += ra[3] * b4.x; acc[3][1] += ra[3] * b4.y;
            acc[3][2] += ra[3] * b4.z; acc[3][3] += ra[3] * b4.w;
        }
        __syncthreads();
    }
    #pragma unroll
    for (int i = 0; i < 4; i++)
        #pragma unroll
        for (int j = 0; j < 4; j++)
            atomicAdd(&g_x[(rowBase + ty * 4 + i) * 192 + tx * 4 + j], acc[i][j]);
}

// ---------------------------------------------------------------------------
// opnn: C[b, d*64+n] = sum_m s[b,m]*Qr[m, d*64+n]; epilogue contracts n with
// s[b,n] in-register (128-col tile = 2 complete d's) -> g_x[:,128:192].
// BM=128, BN=128, BK=32, TM=8, TN=8. grid (32, 32).
// ---------------------------------------------------------------------------
__global__ void __launch_bounds__(256) opnn_kernel()
{
    __shared__ float smem[128 * 36 + 32 * 132];   // As[128][36] | Bs[32][132]; aliased Sep[128][68]
    float (*As)[36]  = reinterpret_cast<float(*)[36]>(smem);
    float (*Bs)[132] = reinterpret_cast<float(*)[132]>(smem + 128 * 36);
    const int tid = threadIdx.x;
    const int tx = tid & 15, ty = tid >> 4;
    const int rowBase = blockIdx.y * 128;
    const int colBase = blockIdx.x * 128;

    float acc[8][8];
    #pragma unroll
    for (int i = 0; i < 8; i++)
        #pragma unroll
        for (int j = 0; j < 8; j++) acc[i][j] = 0.f;

    for (int k0 = 0; k0 < 64; k0 += 32) {
        {
            const int k = tid & 31, r0 = tid >> 5;
            #pragma unroll
            for (int p = 0; p < 16; p++) {
                int r = r0 + p * 8;
                As[r][k] = g_s[(rowBase + r) * 64 + k0 + k];
            }
        }
        {
            const int c = tid & 127, kl = tid >> 7;
            #pragma unroll
            for (int p = 0; p < 16; p++) {
                int k = kl + p * 2;
                Bs[k][c] = g_qr[(k0 + k) * 4096 + colBase + c];
            }
        }
        __syncthreads();
        #pragma unroll 4
        for (int kk = 0; kk < 32; kk++) {
            float ra[8];
            #pragma unroll
            for (int i = 0; i < 8; i++) ra[i] = As[ty * 8 + i][kk];
            float4 b0 = *reinterpret_cast<const float4*>(&Bs[kk][tx * 8]);
            float4 b1 = *reinterpret_cast<const float4*>(&Bs[kk][tx * 8 + 4]);
            float rb[8] = {b0.x, b0.y, b0.z, b0.w, b1.x, b1.y, b1.z, b1.w};
            #pragma unroll
            for (int i = 0; i < 8; i++)
                #pragma unroll
                for (int j = 0; j < 8; j++)
                    acc[i][j] += ra[i] * rb[j];
        }
        __syncthreads();
    }

    // re-stage the full s tile (aliases As/Bs; acc lives in registers)
    float (*Sep)[68] = reinterpret_cast<float(*)[68]>(smem);
    {
        const int n = tid & 63, r0 = tid >> 6;
        #pragma unroll
        for (int p = 0; p < 32; p++) {
            int r = r0 + p * 4;
            Sep[r][n] = g_s[(rowBase + r) * 64 + n];
        }
    }
    __syncthreads();

    const int d = (colBase >> 6) + (tx >> 3);
    #pragma unroll
    for (int i = 0; i < 8; i++) {
        const int r = ty * 8 + i;
        float part = 0.f;
        #pragma unroll
        for (int j = 0; j < 8; j++) {
            int nn = (tx * 8 + j) & 63;
            part += acc[i][j] * Sep[r][nn];
        }
        part += __shfl_xor_sync(0xffffffffu, part, 1);
        part += __shfl_xor_sync(0xffffffffu, part, 2);
        part += __shfl_xor_sync(0xffffffffu, part, 4);
        if ((tx & 7) == 0)
            g_x[(rowBase + r) * 192 + 128 + d] = part;
    }
}

// ---------------------------------------------------------------------------
// MLP GEMM: C = A[M,K] @ B[K,N] with fused BN(inference)+ReLU epilogue.
// BM=64, BN=64, BK=32, TM=4, TN=4, 256 threads. grid (N/64, M/64).
// ---------------------------------------------------------------------------
template<int EPI>
__global__ void __launch_bounds__(256) mlp_gemm(const float* __restrict__ A,
                                                const float* __restrict__ B,
                                                float* __restrict__ C,
                                                int K, int N,
                                                const float* __restrict__ bias,
                                                const float* __restrict__ gam,
                                                const float* __restrict__ bet,
                                                const float* __restrict__ mu,
                                                const float* __restrict__ var)
{
    __shared__ float As[64][36];   // [b][k]
    __shared__ float Bs[32][68];   // [k][n]
    const int tid = threadIdx.x;
    const int tx = tid & 15, ty = tid >> 4;
    const int rowBase = blockIdx.y * 64;
    const int colBase = blockIdx.x * 64;

    float acc[4][4];
    #pragma unroll
    for (int i = 0; i < 4; i++)
        #pragma unroll
        for (int j = 0; j < 4; j++) acc[i][j] = 0.f;

    for (int k0 = 0; k0 < K; k0 += 32) {
        {
            const int k = tid & 31, r0 = tid >> 5;
            #pragma unroll
            for (int p = 0; p < 8; p++) {
                int r = r0 + p * 8;
                As[r][k] = A[(rowBase + r) * K + k0 + k];
            }
        }
        {
            const int c = tid & 63, kl = tid >> 6;
            #pragma unroll
            for (int p = 0; p < 8; p++) {
                int k = kl + p * 4;
                Bs[k][c] = B[(k0 + k) * N + colBase + c];
            }
        }
        __syncthreads();
        #pragma unroll 8
        for (int kk = 0; kk < 32; kk++) {
            float ra[4];
            #pragma unroll
            for (int i = 0; i < 4; i++) ra[i] = As[ty * 4 + i][kk];
            float4 b4 = *reinterpret_cast<const float4*>(&Bs[kk][tx * 4]);
            acc[0][0] += ra[0] * b4.x; acc[0][1] += ra[0] * b4.y;
            acc[0][2] += ra[0] * b4.z; acc[0][3] += ra[0] * b4.w;
            acc[1][0] += ra[1] * b4.x; acc[1][1] += ra[1] * b4.y;
            acc[1][2] += ra[1] * b4.z; acc[1][3] += ra[1] * b4.w;
            acc[2][0] += ra[2] * b4.x; acc[2][1] += ra[2] * b4.y;
            acc[2][2] += ra[2] * b4.z; acc[2][3] += ra[2] * b4.w;
            acc[3][0] += ra[3] * b4.x; acc[3][1] += ra[3] * b4.y;
            acc[3][2] += ra[3] * b4.z; acc[3][3] += ra[3] * b4.w;
        }
        __syncthreads();
    }

    #pragma unroll
    for (int j = 0; j < 4; j++) {
        const int col = colBase + tx * 4 + j;
        float scale = 1.f, shift = 0.f;
        if (EPI == 1) {
            scale = gam[col] * rsqrtf(var[col] + 1e-3f);
            shift = (bias[col] - mu[col]) * scale + bet[col];
        }
        #pragma unroll
        for (int i = 0; i < 4; i++) {
            const int row = rowBase + ty * 4 + i;
            float v = acc[i][j];
            if (EPI == 1) v = fmaxf(v * scale + shift, 0.f);
            C[row * N + col] = v;
        }
    }
}

// ---------------------------------------------------------------------------
// Final dense [4096,128]@[128,1] + sigmoid; one warp per row
// ---------------------------------------------------------------------------
__global__ void final_kernel(const float* __restrict__ Wout,
                             const float* __restrict__ bout,
                             float* __restrict__ out)
{
    const int warp = (blockIdx.x * blockDim.x + threadIdx.x) >> 5;
    const int lane = threadIdx.x & 31;
    if (warp >= BATCH) return;
    const float* h = &g_h2[warp * 128];
    float acc = h[lane]      * Wout[lane]
              + h[lane + 32] * Wout[lane + 32]
              + h[lane + 64] * Wout[lane + 64]
              + h[lane + 96] * Wout[lane + 96];
    #pragma unroll
    for (int off = 16; off > 0; off >>= 1)
        acc += __shfl_down_sync(0xffffffffu, acc, off);
    if (lane == 0) {
        float z = acc + bout[0];
        out[warp] = 1.f / (1.f + expf(-z));
    }
}

// ---------------------------------------------------------------------------
extern "C" void kernel_launch(void* const* d_in, const int* in_sizes, int n_in,
                              void* d_out, int out_size)
{
    const float* fv    = (const float*)d_in[0];
    const int*   idx   = (const int*)  d_in[1];
    const float* emb   = (const float*)d_in[2];
    const float* LS    = (const float*)d_in[3];
    const float* theta = (const float*)d_in[4];
    const float* quad  = (const float*)d_in[5];
    const float* W0  = (const float*)d_in[6];
    const float* b0  = (const float*)d_in[7];
    const float* gm0 = (const float*)d_in[8];
    const float* be0 = (const float*)d_in[9];
    const float* m0  = (const float*)d_in[10];
    const float* v0  = (const float*)d_in[11];
    const float* W1  = (const float*)d_in[12];
    const float* b1  = (const float*)d_in[13];
    const float* gm1 = (const float*)d_in[14];
    const float* be1 = (const float*)d_in[15];
    const float* m1  = (const float*)d_in[16];
    const float* v1  = (const float*)d_in[17];
    const float* W2  = (const float*)d_in[18];
    const float* b2  = (const float*)d_in[19];
    const float* gm2 = (const float*)d_in[20];
    const float* be2 = (const float*)d_in[21];
    const float* m2  = (const float*)d_in[22];
    const float* v2  = (const float*)d_in[23];
    const float* Wout = (const float*)d_in[24];
    const float* bout = (const float*)d_in[25];
    float* out = (float*)d_out;

    float *p_x, *p_h0, *p_h1, *p_h2;
    cudaGetSymbolAddress((void**)&p_x,  g_x);
    cudaGetSymbolAddress((void**)&p_h0, g_h0);
    cudaGetSymbolAddress((void**)&p_h1, g_h1);
    cudaGetSymbolAddress((void**)&p_h2, g_h2);

    // 1) s / sq -> l_p_in; zero l_z
    gather_kernel<<<BATCH, 256>>>(fv, idx, emb, theta);
    // 2) quad transpose for opnn
    prep_qr_kernel<<<1024, 256>>>(quad);
    // 3) l_z fused gather-GEMM (atomic accumulate over 5 n-chunks)
    lz_kernel<<<dim3(64, 5), 256>>>(fv, idx, emb, LS);
    // 4) opnn fused GEMM+contraction
    opnn_kernel<<<dim3(32, 32), 256>>>();
    // 5) MLP
    mlp_gemm<1><<<dim3(512 / 64, BATCH / 64), 256>>>(p_x,  W0, p_h0, 192, 512, b0, gm0, be0, m0, v0);
    mlp_gemm<1><<<dim3(256 / 64, BATCH / 64), 256>>>(p_h0, W1, p_h1, 512, 256, b1, gm1, be1, m1, v1);
    mlp_gemm<1><<<dim3(128 / 64, BATCH / 64), 256>>>(p_h1, W2, p_h2, 256, 128, b2, gm2, be2, m2, v2);
    // 6) output + sigmoid
    final_kernel<<<BATCH * 32 / 256, 256>>>(Wout, bout, out);
}

// round 4
// speedup vs baseline: 4.7545x; 1.7154x over previous
#include <cuda_runtime.h>
#include <cuda_bf16.h>
#include <cstdint>
#include <math.h>

#define BATCH 4096

// ---------------- device scratch (no allocations allowed) ------------------
__device__ float g_s[4096 * 64];
__device__ float g_x[4096 * 192];
__device__ __align__(16) __nv_bfloat16 g_xh[4096 * 192], g_xl[4096 * 192];
__device__ __align__(16) __nv_bfloat16 g_h0h[4096 * 512], g_h0l[4096 * 512];
__device__ __align__(16) __nv_bfloat16 g_h1h[4096 * 256], g_h1l[4096 * 256];
__device__ float g_h2[4096 * 128];
__device__ __align__(16) __nv_bfloat16 g_w0h[512 * 192], g_w0l[512 * 192];
__device__ __align__(16) __nv_bfloat16 g_w1h[256 * 512], g_w1l[256 * 512];
__device__ __align__(16) __nv_bfloat16 g_w2h[128 * 256], g_w2l[128 * 256];

// ---------------- smem tile layout (dynamic smem) ---------------------------
// A_hi [128][72] bf16 (row pitch 144B = 9 x 16B -> ldmatrix conflict-free)
// A_lo, B_hi [64][72], B_lo, then kernel extras.
#define OFF_AH 0
#define OFF_AL 18432
#define OFF_BH 36864
#define OFF_BL 46080
#define OFF_EXT 55296
#define PITCH 144

__device__ __forceinline__ uint32_t smem_u32(const void* p) {
    uint32_t a;
    asm("{ .reg .u64 t; cvta.to.shared.u64 t, %1; cvt.u32.u64 %0, t; }" : "=r"(a) : "l"(p));
    return a;
}

__device__ __forceinline__ void split2(float a, float b, uint32_t& h, uint32_t& l) {
    __nv_bfloat162 hh = __floats2bfloat162_rn(a, b);
    float ra = a - __bfloat162float(hh.x);
    float rb = b - __bfloat162float(hh.y);
    __nv_bfloat162 ll = __floats2bfloat162_rn(ra, rb);
    h = *reinterpret_cast<uint32_t*>(&hh);
    l = *reinterpret_cast<uint32_t*>(&ll);
}

// split 4 consecutive fp32 -> hi/lo bf16 pairs into tile row r, col group c4
__device__ __forceinline__ void put4(char* hi, char* lo, int r, int c4, float4 v) {
    uint32_t h0, l0, h1, l1;
    split2(v.x, v.y, h0, l0);
    split2(v.z, v.w, h1, l1);
    *reinterpret_cast<uint2*>(hi + r * PITCH + c4 * 2) = make_uint2(h0, h1);
    *reinterpret_cast<uint2*>(lo + r * PITCH + c4 * 2) = make_uint2(l0, l1);
}

__device__ __forceinline__ void ldsm4(uint32_t* r, uint32_t addr) {
    asm volatile("ldmatrix.sync.aligned.m8n8.x4.shared.b16 {%0,%1,%2,%3}, [%4];"
                 : "=r"(r[0]), "=r"(r[1]), "=r"(r[2]), "=r"(r[3]) : "r"(addr));
}

__device__ __forceinline__ void mma16816(float* c, const uint32_t* a, const uint32_t* b) {
    asm volatile(
        "mma.sync.aligned.m16n8k16.row.col.f32.bf16.bf16.f32 "
        "{%0,%1,%2,%3}, {%4,%5,%6,%7}, {%8,%9}, {%0,%1,%2,%3};"
        : "+f"(c[0]), "+f"(c[1]), "+f"(c[2]), "+f"(c[3])
        : "r"(a[0]), "r"(a[1]), "r"(a[2]), "r"(a[3]), "r"(b[0]), "r"(b[1]));
}

// warp computes its 16x64 C tile for one K=64 stage with 3-product bf16 split
__device__ __forceinline__ void warp_compute(uint32_t sb, int lane, int wrow, float acc[8][4]) {
    #pragma unroll
    for (int ks = 0; ks < 4; ks++) {
        const int k0 = ks * 16;
        uint32_t aAddr = sb + OFF_AH + (wrow + (lane & 15)) * PITCH
                       + (k0 + ((lane >> 4) & 1) * 8) * 2;
        uint32_t ah[4], al[4];
        ldsm4(ah, aAddr);
        ldsm4(al, aAddr + (OFF_AL - OFF_AH));
        #pragma unroll
        for (int np = 0; np < 4; np++) {
            // x4 covers two n-tiles (np*2, np*2+1), each {k-lo, k-hi} fragment
            uint32_t bAddr = sb + OFF_BH
                           + (np * 16 + ((lane >> 4) & 1) * 8 + (lane & 7)) * PITCH
                           + (k0 + ((lane >> 3) & 1) * 8) * 2;
            uint32_t bh[4], bl[4];
            ldsm4(bh, bAddr);
            ldsm4(bl, bAddr + (OFF_BL - OFF_BH));
            mma16816(acc[np * 2],     ah, bh);
            mma16816(acc[np * 2],     ah, bl);
            mma16816(acc[np * 2],     al, bh);
            mma16816(acc[np * 2 + 1], ah, bh + 2);
            mma16816(acc[np * 2 + 1], ah, bl + 2);
            mma16816(acc[np * 2 + 1], al, bh + 2);
        }
    }
}

// ---------------------------------------------------------------------------
// gather: s[b,m], l_p_in -> g_x[:,64:128]; zero l_z / l_p_out accum slots
// ---------------------------------------------------------------------------
__global__ void gather_kernel(const float* __restrict__ fv,
                              const int* __restrict__ idx,
                              const float* __restrict__ emb,
                              const float* __restrict__ theta)
{
    const int b = blockIdx.x;
    const int t = threadIdx.x;
    __shared__ float feats[50 * 65];
    __shared__ float sq[50];
    __shared__ int   sidx[50];
    __shared__ float sfv[50];

    if (t < 50) { sidx[t] = idx[b * 50 + t]; sfv[t] = fv[b * 50 + t]; }
    __syncthreads();
    for (int j = t; j < 3200; j += 256) {
        int n = j >> 6, m = j & 63;
        feats[n * 65 + m] = emb[(long)sidx[n] * 64 + m] * sfv[n];
    }
    __syncthreads();
    if (t < 64) {
        float acc = 0.f;
        #pragma unroll
        for (int n = 0; n < 50; n++) acc += feats[n * 65 + t];
        g_s[b * 64 + t] = acc;
        g_x[b * 192 + t] = 0.f;
        g_x[b * 192 + 128 + t] = 0.f;
    }
    if (t >= 64 && t < 114) {
        int n = t - 64;
        float acc = 0.f;
        #pragma unroll
        for (int m = 0; m < 64; m++) { float v = feats[n * 65 + m]; acc += v * v; }
        sq[n] = acc;
    }
    __syncthreads();
    if (t < 64) {
        float acc = 0.f;
        #pragma unroll
        for (int n = 0; n < 50; n++) { float th = theta[t * 50 + n]; acc += th * th * sq[n]; }
        g_x[b * 192 + 64 + t] = acc;
    }
}

// ---------------------------------------------------------------------------
// weight transpose + split: W[K,N] fp32 -> Wt_hi/Wt_lo [N,K] bf16
// ---------------------------------------------------------------------------
__global__ void prep_w(const float* __restrict__ W, __nv_bfloat16* __restrict__ th,
                       __nv_bfloat16* __restrict__ tl, int K, int N)
{
    int o = blockIdx.x * 256 + threadIdx.x;
    if (o >= K * N) return;
    int n = o / K, k = o % K;
    float v = W[k * N + n];
    __nv_bfloat16 h = __float2bfloat16_rn(v);
    th[o] = h;
    tl[o] = __float2bfloat16_rn(v - __bfloat162float(h));
}

// ---------------------------------------------------------------------------
// convert concat features g_x -> bf16 hi/lo pair
// ---------------------------------------------------------------------------
__global__ void convert_x()
{
    int o = blockIdx.x * 256 + threadIdx.x;   // 786432
    float v = g_x[o];
    __nv_bfloat16 h = __float2bfloat16_rn(v);
    g_xh[o] = h;
    g_xl[o] = __float2bfloat16_rn(v - __bfloat162float(h));
}

// ---------------------------------------------------------------------------
// l_z: C[b,d] += sum_k feats[b,k] * LS[d,k]; fused gather A-gen.
// grid (32 row-tiles, 5 k-splits), 10 stages of BK=64 (one field n each).
// ---------------------------------------------------------------------------
__global__ void __launch_bounds__(256) lz_mma(const float* __restrict__ fv,
                                              const int* __restrict__ idx,
                                              const float* __restrict__ emb,
                                              const float* __restrict__ LS)
{
    extern __shared__ char sm[];
    const int tid = threadIdx.x, wid = tid >> 5, lane = tid & 31;
    const uint32_t sb = smem_u32(sm);
    int*   sidx = reinterpret_cast<int*>(sm + OFF_EXT);
    float* sfv  = reinterpret_cast<float*>(sm + OFF_EXT + 5120);
    const int rowBase = blockIdx.x * 128;
    const int nBase = blockIdx.y * 10;
    const int wrow = wid * 16;

    if (tid < 128) {
        #pragma unroll
        for (int ni = 0; ni < 10; ni++) {
            sidx[ni * 128 + tid] = idx[(rowBase + tid) * 50 + nBase + ni];
            sfv [ni * 128 + tid] = fv[(rowBase + tid) * 50 + nBase + ni];
        }
    }

    float acc[8][4];
    #pragma unroll
    for (int i = 0; i < 8; i++)
        #pragma unroll
        for (int j = 0; j < 4; j++) acc[i][j] = 0.f;

    for (int ni = 0; ni < 10; ni++) {
        const int n = nBase + ni;
        __syncthreads();   // prev compute done (also covers sidx preload on ni=0)
        #pragma unroll
        for (int p = 0; p < 8; p++) {
            int j = tid + p * 256;
            int r = j >> 4, c4 = (j & 15) * 4;
            float4 e = *reinterpret_cast<const float4*>(&emb[(long)sidx[ni * 128 + r] * 64 + c4]);
            float s = sfv[ni * 128 + r];
            put4(sm + OFF_AH, sm + OFF_AL, r, c4,
                 make_float4(e.x * s, e.y * s, e.z * s, e.w * s));
        }
        #pragma unroll
        for (int p = 0; p < 4; p++) {
            int j = tid + p * 256;
            int d = j >> 4, c4 = (j & 15) * 4;
            float4 v = *reinterpret_cast<const float4*>(&LS[d * 3200 + n * 64 + c4]);
            put4(sm + OFF_BH, sm + OFF_BL, d, c4, v);
        }
        __syncthreads();
        warp_compute(sb, lane, wrow, acc);
    }

    const int row0 = rowBase + wrow + (lane >> 2);
    #pragma unroll
    for (int nt = 0; nt < 8; nt++) {
        const int col = nt * 8 + (lane & 3) * 2;
        atomicAdd(&g_x[row0 * 192 + col],           acc[nt][0]);
        atomicAdd(&g_x[row0 * 192 + col + 1],       acc[nt][1]);
        atomicAdd(&g_x[(row0 + 8) * 192 + col],     acc[nt][2]);
        atomicAdd(&g_x[(row0 + 8) * 192 + col + 1], acc[nt][3]);
    }
}

// ---------------------------------------------------------------------------
// l_p_out: C[b,d] += sum_k s[b,m(k)]*s[b,n(k)] * quad[d,k], k=m*64+n.
// grid (32 row-tiles, 8 k-splits of 8 m-values). A generated from s tile.
// ---------------------------------------------------------------------------
__global__ void __launch_bounds__(256) opnn_mma(const float* __restrict__ quad)
{
    extern __shared__ char sm[];
    const int tid = threadIdx.x, wid = tid >> 5, lane = tid & 31;
    const uint32_t sb = smem_u32(sm);
    float* st = reinterpret_cast<float*>(sm + OFF_EXT);   // [128][68]
    const int rowBase = blockIdx.x * 128;
    const int m0 = blockIdx.y * 8;
    const int wrow = wid * 16;

    #pragma unroll
    for (int p = 0; p < 8; p++) {
        int j = tid + p * 256;
        int r = j >> 4, c4 = (j & 15) * 4;
        *reinterpret_cast<float4*>(&st[r * 68 + c4]) =
            *reinterpret_cast<const float4*>(&g_s[(rowBase + r) * 64 + c4]);
    }

    float acc[8][4];
    #pragma unroll
    for (int i = 0; i < 8; i++)
        #pragma unroll
        for (int j = 0; j < 4; j++) acc[i][j] = 0.f;

    for (int mi = 0; mi < 8; mi++) {
        const int m = m0 + mi;
        __syncthreads();
        #pragma unroll
        for (int p = 0; p < 8; p++) {
            int j = tid + p * 256;
            int r = j >> 4, c4 = (j & 15) * 4;
            float sv = st[r * 68 + m];
            float4 v = *reinterpret_cast<const float4*>(&st[r * 68 + c4]);
            put4(sm + OFF_AH, sm + OFF_AL, r, c4,
                 make_float4(v.x * sv, v.y * sv, v.z * sv, v.w * sv));
        }
        #pragma unroll
        for (int p = 0; p < 4; p++) {
            int j = tid + p * 256;
            int d = j >> 4, c4 = (j & 15) * 4;
            float4 v = *reinterpret_cast<const float4*>(&quad[d * 4096 + m * 64 + c4]);
            put4(sm + OFF_BH, sm + OFF_BL, d, c4, v);
        }
        __syncthreads();
        warp_compute(sb, lane, wrow, acc);
    }

    const int row0 = rowBase + wrow + (lane >> 2);
    #pragma unroll
    for (int nt = 0; nt < 8; nt++) {
        const int col = 128 + nt * 8 + (lane & 3) * 2;
        atomicAdd(&g_x[row0 * 192 + col],           acc[nt][0]);
        atomicAdd(&g_x[row0 * 192 + col + 1],       acc[nt][1]);
        atomicAdd(&g_x[(row0 + 8) * 192 + col],     acc[nt][2]);
        atomicAdd(&g_x[(row0 + 8) * 192 + col + 1], acc[nt][3]);
    }
}

// ---------------------------------------------------------------------------
// MLP layer: C = A @ W^T + BN + ReLU. A bf16 hi/lo [M,K]; W split [N,K].
// OUT_SPLIT=1 writes bf16 hi/lo activations; 0 writes fp32.
// grid (N/64, 32).
// ---------------------------------------------------------------------------
template<int OUT_SPLIT>
__global__ void __launch_bounds__(256) mlp_mma(
    const __nv_bfloat16* __restrict__ ah, const __nv_bfloat16* __restrict__ al,
    const __nv_bfloat16* __restrict__ wh, const __nv_bfloat16* __restrict__ wl,
    __nv_bfloat16* __restrict__ oh, __nv_bfloat16* __restrict__ ol,
    float* __restrict__ of, int K, int N,
    const float* __restrict__ bias, const float* __restrict__ gam,
    const float* __restrict__ bet, const float* __restrict__ mu,
    const float* __restrict__ var)
{
    extern __shared__ char sm[];
    const int tid = threadIdx.x, wid = tid >> 5, lane = tid & 31;
    const uint32_t sb = smem_u32(sm);
    float* sscale = reinterpret_cast<float*>(sm + OFF_EXT);
    float* sshift = sscale + 64;
    const int rowBase = blockIdx.y * 128;
    const int colBase = blockIdx.x * 64;
    const int wrow = wid * 16;

    if (tid < 64) {
        int c = colBase + tid;
        float sc = gam[c] * rsqrtf(var[c] + 1e-3f);
        sscale[tid] = sc;
        sshift[tid] = (bias[c] - mu[c]) * sc + bet[c];
    }

    float acc[8][4];
    #pragma unroll
    for (int i = 0; i < 8; i++)
        #pragma unroll
        for (int j = 0; j < 4; j++) acc[i][j] = 0.f;

    const int nch = K >> 6;
    for (int ch = 0; ch < nch; ch++) {
        const int k0 = ch * 64;
        __syncthreads();
        #pragma unroll
        for (int p = 0; p < 8; p++) {
            int j = tid + p * 256;
            int r = j >> 4, c8 = (j & 15) * 4;
            long off = (long)(rowBase + r) * K + k0 + c8;
            *reinterpret_cast<uint2*>(sm + OFF_AH + r * PITCH + c8 * 2) =
                *reinterpret_cast<const uint2*>(&ah[off]);
            *reinterpret_cast<uint2*>(sm + OFF_AL + r * PITCH + c8 * 2) =
                *reinterpret_cast<const uint2*>(&al[off]);
        }
        #pragma unroll
        for (int p = 0; p < 4; p++) {
            int j = tid + p * 256;
            int d = j >> 4, c8 = (j & 15) * 4;
            long off = (long)(colBase + d) * K + k0 + c8;
            *reinterpret_cast<uint2*>(sm + OFF_BH + d * PITCH + c8 * 2) =
                *reinterpret_cast<const uint2*>(&wh[off]);
            *reinterpret_cast<uint2*>(sm + OFF_BL + d * PITCH + c8 * 2) =
                *reinterpret_cast<const uint2*>(&wl[off]);
        }
        __syncthreads();
        warp_compute(sb, lane, wrow, acc);
    }
    __syncthreads();   // sscale/sshift visible

    const int row0 = rowBase + wrow + (lane >> 2);
    #pragma unroll
    for (int nt = 0; nt < 8; nt++) {
        const int cl = nt * 8 + (lane & 3) * 2;
        const float s0 = sscale[cl], s1 = sscale[cl + 1];
        const float t0 = sshift[cl], t1 = sshift[cl + 1];
        float v0 = fmaxf(acc[nt][0] * s0 + t0, 0.f);
        float v1 = fmaxf(acc[nt][1] * s1 + t1, 0.f);
        float v2 = fmaxf(acc[nt][2] * s0 + t0, 0.f);
        float v3 = fmaxf(acc[nt][3] * s1 + t1, 0.f);
        if (OUT_SPLIT) {
            uint32_t h, l;
            split2(v0, v1, h, l);
            *reinterpret_cast<uint32_t*>(&oh[(long)row0 * N + colBase + cl]) = h;
            *reinterpret_cast<uint32_t*>(&ol[(long)row0 * N + colBase + cl]) = l;
            split2(v2, v3, h, l);
            *reinterpret_cast<uint32_t*>(&oh[(long)(row0 + 8) * N + colBase + cl]) = h;
            *reinterpret_cast<uint32_t*>(&ol[(long)(row0 + 8) * N + colBase + cl]) = l;
        } else {
            *reinterpret_cast<float2*>(&of[(long)row0 * N + colBase + cl]) = make_float2(v0, v1);
            *reinterpret_cast<float2*>(&of[(long)(row0 + 8) * N + colBase + cl]) = make_float2(v2, v3);
        }
    }
}

// ---------------------------------------------------------------------------
// final dense [4096,128]@[128,1] + sigmoid
// ---------------------------------------------------------------------------
__global__ void final_kernel(const float* __restrict__ Wout,
                             const float* __restrict__ bout,
                             float* __restrict__ out)
{
    const int warp = (blockIdx.x * blockDim.x + threadIdx.x) >> 5;
    const int lane = threadIdx.x & 31;
    if (warp >= BATCH) return;
    const float* h = &g_h2[warp * 128];
    float acc = h[lane]      * Wout[lane]
              + h[lane + 32] * Wout[lane + 32]
              + h[lane + 64] * Wout[lane + 64]
              + h[lane + 96] * Wout[lane + 96];
    #pragma unroll
    for (int off = 16; off > 0; off >>= 1)
        acc += __shfl_down_sync(0xffffffffu, acc, off);
    if (lane == 0) {
        float z = acc + bout[0];
        out[warp] = 1.f / (1.f + expf(-z));
    }
}

// ---------------------------------------------------------------------------
extern "C" void kernel_launch(void* const* d_in, const int* in_sizes, int n_in,
                              void* d_out, int out_size)
{
    const float* fv    = (const float*)d_in[0];
    const int*   idx   = (const int*)  d_in[1];
    const float* emb   = (const float*)d_in[2];
    const float* LS    = (const float*)d_in[3];
    const float* theta = (const float*)d_in[4];
    const float* quad  = (const float*)d_in[5];
    const float* W0  = (const float*)d_in[6];
    const float* b0  = (const float*)d_in[7];
    const float* gm0 = (const float*)d_in[8];
    const float* be0 = (const float*)d_in[9];
    const float* m0  = (const float*)d_in[10];
    const float* v0  = (const float*)d_in[11];
    const float* W1  = (const float*)d_in[12];
    const float* b1  = (const float*)d_in[13];
    const float* gm1 = (const float*)d_in[14];
    const float* be1 = (const float*)d_in[15];
    const float* m1  = (const float*)d_in[16];
    const float* v1  = (const float*)d_in[17];
    const float* W2  = (const float*)d_in[18];
    const float* b2  = (const float*)d_in[19];
    const float* gm2 = (const float*)d_in[20];
    const float* be2 = (const float*)d_in[21];
    const float* m2  = (const float*)d_in[22];
    const float* v2  = (const float*)d_in[23];
    const float* Wout = (const float*)d_in[24];
    const float* bout = (const float*)d_in[25];
    float* out = (float*)d_out;

    __nv_bfloat16 *p_xh, *p_xl, *p_h0h, *p_h0l, *p_h1h, *p_h1l;
    __nv_bfloat16 *p_w0h, *p_w0l, *p_w1h, *p_w1l, *p_w2h, *p_w2l;
    float *p_h2;
    cudaGetSymbolAddress((void**)&p_xh,  g_xh);
    cudaGetSymbolAddress((void**)&p_xl,  g_xl);
    cudaGetSymbolAddress((void**)&p_h0h, g_h0h);
    cudaGetSymbolAddress((void**)&p_h0l, g_h0l);
    cudaGetSymbolAddress((void**)&p_h1h, g_h1h);
    cudaGetSymbolAddress((void**)&p_h1l, g_h1l);
    cudaGetSymbolAddress((void**)&p_h2,  g_h2);
    cudaGetSymbolAddress((void**)&p_w0h, g_w0h);
    cudaGetSymbolAddress((void**)&p_w0l, g_w0l);
    cudaGetSymbolAddress((void**)&p_w1h, g_w1h);
    cudaGetSymbolAddress((void**)&p_w1l, g_w1l);
    cudaGetSymbolAddress((void**)&p_w2h, g_w2h);
    cudaGetSymbolAddress((void**)&p_w2l, g_w2l);

    const int SMEM_LZ  = OFF_EXT + 10240;          // sidx/sfv for 10 stages
    const int SMEM_OP  = OFF_EXT + 128 * 68 * 4;   // s tile
    const int SMEM_MLP = OFF_EXT + 512;            // scale/shift
    cudaFuncSetAttribute(lz_mma,     cudaFuncAttributeMaxDynamicSharedMemorySize, SMEM_LZ);
    cudaFuncSetAttribute(opnn_mma,   cudaFuncAttributeMaxDynamicSharedMemorySize, SMEM_OP);
    cudaFuncSetAttribute(mlp_mma<1>, cudaFuncAttributeMaxDynamicSharedMemorySize, SMEM_MLP);
    cudaFuncSetAttribute(mlp_mma<0>, cudaFuncAttributeMaxDynamicSharedMemorySize, SMEM_MLP);

    // 1) s, l_p_in, zero accumulation slots
    gather_kernel<<<BATCH, 256>>>(fv, idx, emb, theta);
    // 2) weight transpose + split
    prep_w<<<(192 * 512 + 255) / 256, 256>>>(W0, p_w0h, p_w0l, 192, 512);
    prep_w<<<(512 * 256 + 255) / 256, 256>>>(W1, p_w1h, p_w1l, 512, 256);
    prep_w<<<(256 * 128 + 255) / 256, 256>>>(W2, p_w2h, p_w2l, 256, 128);
    // 3) l_z (tensor core, fused gather)
    lz_mma<<<dim3(32, 5), 256, SMEM_LZ>>>(fv, idx, emb, LS);
    // 4) l_p_out (tensor core, outer-product A-gen)
    opnn_mma<<<dim3(32, 8), 256, SMEM_OP>>>(quad);
    // 5) split-convert concat features
    convert_x<<<4096 * 192 / 256, 256>>>();
    // 6) MLP
    mlp_mma<1><<<dim3(8, 32), 256, SMEM_MLP>>>(p_xh, p_xl, p_w0h, p_w0l,
        p_h0h, p_h0l, nullptr, 192, 512, b0, gm0, be0, m0, v0);
    mlp_mma<1><<<dim3(4, 32), 256, SMEM_MLP>>>(p_h0h, p_h0l, p_w1h, p_w1l,
        p_h1h, p_h1l, nullptr, 512, 256, b1, gm1, be1, m1, v1);
    mlp_mma<0><<<dim3(2, 32), 256, SMEM_MLP>>>(p_h1h, p_h1l, p_w2h, p_w2l,
        nullptr, nullptr, p_h2, 256, 128, b2, gm2, be2, m2, v2);
    // 7) output + sigmoid
    final_kernel<<<BATCH * 32 / 256, 256>>>(Wout, bout, out);
}